// round 2
// baseline (speedup 1.0000x reference)
#include <cuda_runtime.h>
#include <math.h>

#define NB   4
#define NC   512
#define FH   64
#define FW   64
#define HWs  4096
#define NANC 9
#define NA   36864        // 4096*9
#define NSORT 65536
#define NIN  6000
#define NWRD 94           // ceil(6000/64)
#define NPAD 6016         // 94*64
#define NOUTP 300

#define OFF_LOCS 294912
#define OFF_ROIS 884736
#define OFF_INDS 889536
#define OFF_ANCH 890736

typedef unsigned long long u64;

// ---------------- scratch (static device globals; no allocation) ----------------
__device__ float g_h[(size_t)NB * NC * HWs];          // 33.5 MB conv output
__device__ float g_rois[(size_t)NB * NA * 4];
__device__ unsigned char g_valid[NB * NA];
__device__ u64 g_keys[NB * NSORT];
__device__ float g_rois_s[NB * NPAD * 4];             // zero-init padding rows stay 0
__device__ unsigned char g_valid_s[NB * NPAD];
__device__ u64 g_mask[(size_t)NB * NIN * NWRD];       // low words never written -> stay 0
__device__ unsigned char g_keep[NB * NIN];

// ---------------- helpers ----------------
__device__ __forceinline__ unsigned int fdesc(float f) {
    unsigned int u = __float_as_uint(f);
    unsigned int asc = (u & 0x80000000u) ? ~u : (u | 0x80000000u);
    return ~asc;  // descending-order sortable key
}

__device__ __forceinline__ void base_anchor(int a, float& y1, float& x1, float& y2, float& x2) {
    int ri = a / 3, si = a % 3;
    double ratio = (ri == 0) ? 0.5 : (ri == 1 ? 1.0 : 2.0);
    double scale = (si == 0) ? 8.0 : (si == 1 ? 16.0 : 32.0);
    double h = 16.0 * scale * sqrt(ratio);
    double w = 16.0 * scale * sqrt(1.0 / ratio);
    y1 = (float)(8.0 - h * 0.5);
    x1 = (float)(8.0 - w * 0.5);
    y2 = (float)(8.0 + h * 0.5);
    x2 = (float)(8.0 + w * 0.5);
}

// ---------------- 3x3 conv + bias + relu (fp32) ----------------
// grid (16 tiles, 16 oc-groups, 4 batch), 256 threads.
// tile = 16x16 spatial, 32 output channels per block, 16 input channels per chunk.
__global__ void __launch_bounds__(256) conv3x3_kernel(const float* __restrict__ x,
                                                      const float* __restrict__ w,
                                                      const float* __restrict__ bias) {
    __shared__ float s_in[16 * 324];   // 16 ch * 18 * 18
    __shared__ float s_w[32 * 145];    // 32 oc * (144 + 1 pad)

    int b = blockIdx.z;
    int ocg = blockIdx.y;
    int ty0 = (blockIdx.x >> 2) << 4;
    int tx0 = (blockIdx.x & 3) << 4;
    int tid = threadIdx.x;
    int t_oc = tid & 7;          // 8 oc lanes
    int t_sp = tid >> 3;         // 32 spatial lanes
    int sy = t_sp >> 4, sx = t_sp & 15;

    float acc[8][4];
#pragma unroll
    for (int p = 0; p < 8; p++)
#pragma unroll
        for (int q = 0; q < 4; q++) acc[p][q] = 0.f;

    const float* xb = x + (size_t)b * NC * HWs;

    for (int cc = 0; cc < NC; cc += 16) {
        __syncthreads();
        for (int idx = tid; idx < 16 * 324; idx += 256) {
            int ch = idx / 324, rem = idx % 324;
            int iy = rem / 18, ix = rem % 18;
            int gy = ty0 + iy - 1, gx = tx0 + ix - 1;
            float v = 0.f;
            if ((unsigned)gy < 64u && (unsigned)gx < 64u)
                v = xb[(size_t)(cc + ch) * HWs + gy * 64 + gx];
            s_in[idx] = v;
        }
        for (int idx = tid; idx < 32 * 144; idx += 256) {
            int ocl = idx / 144, r = idx % 144;
            s_w[ocl * 145 + r] = w[(size_t)(ocg * 32 + ocl) * 4608 + cc * 9 + r];
        }
        __syncthreads();

#pragma unroll
        for (int ic = 0; ic < 16; ic++) {
#pragma unroll
            for (int t = 0; t < 9; t++) {
                int ky = t / 3, kx = t % 3;
                float w0 = s_w[(t_oc + 0) * 145 + ic * 9 + t];
                float w1 = s_w[(t_oc + 8) * 145 + ic * 9 + t];
                float w2 = s_w[(t_oc + 16) * 145 + ic * 9 + t];
                float w3 = s_w[(t_oc + 24) * 145 + ic * 9 + t];
                const float* sp = &s_in[ic * 324 + (sy + ky) * 18 + sx + kx];
#pragma unroll
                for (int p = 0; p < 8; p++) {
                    float v = sp[p * 36];
                    acc[p][0] = fmaf(v, w0, acc[p][0]);
                    acc[p][1] = fmaf(v, w1, acc[p][1]);
                    acc[p][2] = fmaf(v, w2, acc[p][2]);
                    acc[p][3] = fmaf(v, w3, acc[p][3]);
                }
            }
        }
    }

#pragma unroll
    for (int q = 0; q < 4; q++) {
        int oc = ocg * 32 + t_oc + 8 * q;
        float bv = bias[oc];
        float* hp = g_h + ((size_t)b * NC + oc) * HWs;
#pragma unroll
        for (int p = 0; p < 8; p++) {
            int py = ty0 + sy + 2 * p, px = tx0 + sx;
            hp[py * 64 + px] = fmaxf(acc[p][q] + bv, 0.f);
        }
    }
}

// ---------------- 1x1 heads + softmax + decode + sort-key pack ----------------
// grid (32, 4), 128 threads; one thread per spatial position.
__global__ void __launch_bounds__(128) heads_kernel(const float* __restrict__ sw,
                                                    const float* __restrict__ sb,
                                                    const float* __restrict__ lw,
                                                    const float* __restrict__ lb,
                                                    float* __restrict__ out) {
    __shared__ float s_w[128 * 54];  // 27.6 KB per chunk
    int b = blockIdx.y;
    int pos = blockIdx.x * 128 + threadIdx.x;

    float acc[54];
#pragma unroll
    for (int o = 0; o < 54; o++) acc[o] = 0.f;

    for (int c0 = 0; c0 < NC; c0 += 128) {
        __syncthreads();
        for (int idx = threadIdx.x; idx < 128 * 54; idx += 128) {
            int o = idx / 128, c = idx % 128;
            float v = (o < 18) ? sw[o * 512 + c0 + c] : lw[(o - 18) * 512 + c0 + c];
            s_w[c * 54 + o] = v;
        }
        __syncthreads();
        const float* hp = g_h + ((size_t)b * NC + c0) * HWs + pos;
        for (int c = 0; c < 128; c++) {
            float v = hp[(size_t)c * HWs];
            const float* wr = &s_w[c * 54];
#pragma unroll
            for (int o = 0; o < 54; o++) acc[o] = fmaf(v, wr[o], acc[o]);
        }
    }

#pragma unroll
    for (int o = 0; o < 18; o++) acc[o] += sb[o];
#pragma unroll
    for (int j = 0; j < 36; j++) acc[18 + j] += lb[j];

    // write rpn_scores / rpn_locs (already in (B, H, W, Cout) order)
    float* os = out + (size_t)(b * HWs + pos) * 18;
#pragma unroll
    for (int o = 0; o < 18; o++) os[o] = acc[o];
    float* ol = out + OFF_LOCS + (size_t)(b * HWs + pos) * 36;
#pragma unroll
    for (int j = 0; j < 36; j++) ol[j] = acc[18 + j];

    int y = pos >> 6, xq = pos & 63;
    float fy = (float)(y * 16), fx = (float)(xq * 16);

#pragma unroll
    for (int a = 0; a < 9; a++) {
        float by1, bx1, by2, bx2;
        base_anchor(a, by1, bx1, by2, bx2);
        float ay1 = fy + by1, ax1 = fx + bx1, ay2 = fy + by2, ax2 = fx + bx2;
        float hA = ay2 - ay1, wA = ax2 - ax1;
        float cy = ay1 + 0.5f * hA, cx = ax1 + 0.5f * wA;
        float dy = acc[18 + 4 * a + 0], dx = acc[18 + 4 * a + 1];
        float dh = acc[18 + 4 * a + 2], dw = acc[18 + 4 * a + 3];
        float cty = dy * hA + cy, ctx = dx * wA + cx;
        float th = expf(dh) * hA, tw = expf(dw) * wA;
        float y1 = cty - 0.5f * th, x1 = ctx - 0.5f * tw;
        float y2 = cty + 0.5f * th, x2 = ctx + 0.5f * tw;
        y1 = fminf(fmaxf(y1, 0.f), 1024.f);
        y2 = fminf(fmaxf(y2, 0.f), 1024.f);
        x1 = fminf(fmaxf(x1, 0.f), 1024.f);
        x2 = fminf(fmaxf(x2, 0.f), 1024.f);
        bool valid = (y2 - y1 >= 16.f) && (x2 - x1 >= 16.f);

        float s0 = acc[2 * a], s1 = acc[2 * a + 1];
        float m = fmaxf(s0, s1);
        float e0 = expf(s0 - m), e1 = expf(s1 - m);
        float fg = e1 / (e0 + e1);
        float skey = valid ? fg : -INFINITY;

        int r = pos * 9 + a;
        size_t ro = ((size_t)b * NA + r) * 4;
        g_rois[ro + 0] = y1; g_rois[ro + 1] = x1;
        g_rois[ro + 2] = y2; g_rois[ro + 3] = x2;
        g_valid[b * NA + r] = valid ? 1 : 0;
        g_keys[(size_t)b * NSORT + r] = ((u64)fdesc(skey) << 32) | (unsigned)r;
    }
}

__global__ void pad_keys_kernel() {
    int gid = blockIdx.x * blockDim.x + threadIdx.x;
    int per = NSORT - NA;  // 28672
    if (gid >= NB * per) return;
    int b = gid / per, i = NA + gid % per;
    g_keys[(size_t)b * NSORT + i] = ~0ull;
}

// ---------------- bitonic sort (ascending on desc-encoded key => score desc, idx asc) ----------------
__global__ void __launch_bounds__(1024) bitonic_local_sort() {
    __shared__ u64 s[4096];
    int base = blockIdx.x * 4096;
#pragma unroll
    for (int m = 0; m < 4; m++) s[threadIdx.x + 1024 * m] = g_keys[base + threadIdx.x + 1024 * m];
    for (int k = 2; k <= 4096; k <<= 1) {
        for (int j = k >> 1; j > 0; j >>= 1) {
            __syncthreads();
#pragma unroll
            for (int m = 0; m < 4; m++) {
                int i = threadIdx.x + 1024 * m;
                int p = i ^ j;
                if (p > i) {
                    int lidx = (base + i) & (NSORT - 1);
                    bool asc = ((lidx & k) == 0);
                    u64 av = s[i], bv = s[p];
                    if (asc ? (av > bv) : (av < bv)) { s[i] = bv; s[p] = av; }
                }
            }
        }
    }
    __syncthreads();
#pragma unroll
    for (int m = 0; m < 4; m++) g_keys[base + threadIdx.x + 1024 * m] = s[threadIdx.x + 1024 * m];
}

__global__ void __launch_bounds__(256) bitonic_global_step(int k, int j) {
    int gid = blockIdx.x * blockDim.x + threadIdx.x;  // NB*NSORT threads
    int seg = gid >> 16, idx = gid & (NSORT - 1);
    int p = idx ^ j;
    if (p > idx) {
        bool asc = ((idx & k) == 0);
        u64* bptr = g_keys + ((size_t)seg << 16);
        u64 av = bptr[idx], bv = bptr[p];
        if (asc ? (av > bv) : (av < bv)) { bptr[idx] = bv; bptr[p] = av; }
    }
}

__global__ void __launch_bounds__(1024) bitonic_local_merge(int k) {
    __shared__ u64 s[4096];
    int base = blockIdx.x * 4096;
    bool asc = (((base & (NSORT - 1)) & k) == 0);
#pragma unroll
    for (int m = 0; m < 4; m++) s[threadIdx.x + 1024 * m] = g_keys[base + threadIdx.x + 1024 * m];
    for (int j = 2048; j > 0; j >>= 1) {
        __syncthreads();
#pragma unroll
        for (int m = 0; m < 4; m++) {
            int i = threadIdx.x + 1024 * m;
            int p = i ^ j;
            if (p > i) {
                u64 av = s[i], bv = s[p];
                if (asc ? (av > bv) : (av < bv)) { s[i] = bv; s[p] = av; }
            }
        }
    }
    __syncthreads();
#pragma unroll
    for (int m = 0; m < 4; m++) g_keys[base + threadIdx.x + 1024 * m] = s[threadIdx.x + 1024 * m];
}

// ---------------- gather top-6000 ----------------
__global__ void gather_kernel() {
    int gid = blockIdx.x * blockDim.x + threadIdx.x;
    if (gid >= NB * NIN) return;
    int b = gid / NIN, i = gid % NIN;
    u64 key = g_keys[(size_t)b * NSORT + i];
    unsigned r = (unsigned)(key & 0xffffffffu);
    size_t src = ((size_t)b * NA + r) * 4;
    size_t dst = ((size_t)b * NPAD + i) * 4;
    g_rois_s[dst + 0] = g_rois[src + 0];
    g_rois_s[dst + 1] = g_rois[src + 1];
    g_rois_s[dst + 2] = g_rois[src + 2];
    g_rois_s[dst + 3] = g_rois[src + 3];
    g_valid_s[b * NPAD + i] = g_valid[b * NA + r];
}

// ---------------- IoU suppression mask (upper-triangular 64x64 tiles) ----------------
__global__ void __launch_bounds__(64) mask_kernel() {
    int rb = blockIdx.x, cb = blockIdx.y, b = blockIdx.z;
    if (cb < rb) return;
    __shared__ float4 sj[64];
    int u = threadIdx.x;
    const float4* rs = (const float4*)g_rois_s;
    sj[u] = rs[(size_t)b * NPAD + cb * 64 + u];
    __syncthreads();
    int i = rb * 64 + u;
    if (i >= NIN) return;
    float4 bi = rs[(size_t)b * NPAD + i];
    float ai = (bi.z - bi.x) * (bi.w - bi.y);
    u64 bits = 0;
#pragma unroll 8
    for (int q = 0; q < 64; q++) {
        int jj = cb * 64 + q;
        if (jj > i) {
            float4 bj = sj[q];
            float yy1 = fmaxf(bi.x, bj.x), xx1 = fmaxf(bi.y, bj.y);
            float yy2 = fminf(bi.z, bj.z), xx2 = fminf(bi.w, bj.w);
            float inter = fmaxf(yy2 - yy1, 0.f) * fmaxf(xx2 - xx1, 0.f);
            float aj = (bj.z - bj.x) * (bj.w - bj.y);
            float iou = inter / (ai + aj - inter + 1e-9f);
            if (iou > 0.7f) bits |= (1ull << q);
        }
    }
    g_mask[((size_t)b * NIN + i) * NWRD + cb] = bits;
}

// ---------------- exact greedy NMS scan (one warp per batch) ----------------
__global__ void __launch_bounds__(32) nms_scan_kernel() {
    int b = blockIdx.x;
    int lane = threadIdx.x;
    const u64* mask = g_mask + (size_t)b * NIN * NWRD;
    const unsigned char* vs = g_valid_s + b * NPAD;
    unsigned char* keep = g_keep + b * NIN;
    int w0 = lane, w1 = lane + 32, w2 = lane + 64;
    bool has2 = (w2 < NWRD);
    u64 r0 = 0, r1 = 0, r2 = 0;

    u64 bufA[8][3], bufB[8][3];
    unsigned char vA[8], vB[8];

#pragma unroll
    for (int t = 0; t < 8; t++) {
        const u64* row = mask + (size_t)t * NWRD;
        bufA[t][0] = row[w0]; bufA[t][1] = row[w1];
        bufA[t][2] = has2 ? row[w2] : 0;
        vA[t] = vs[t];
    }

    for (int base = 0; base < NIN; base += 16) {
        // prefetch [base+8, base+16) into B
#pragma unroll
        for (int t = 0; t < 8; t++) {
            int ri = base + 8 + t;
            if (ri < NIN) {
                const u64* row = mask + (size_t)ri * NWRD;
                bufB[t][0] = row[w0]; bufB[t][1] = row[w1];
                bufB[t][2] = has2 ? row[w2] : 0;
                vB[t] = vs[ri];
            } else { bufB[t][0] = bufB[t][1] = bufB[t][2] = 0; vB[t] = 0; }
        }
        // process A
#pragma unroll
        for (int t = 0; t < 8; t++) {
            int i = base + t;
            int iw = i >> 6;
            int sel = iw >> 5, owner = iw & 31;
            u64 myw = (sel == 0) ? r0 : ((sel == 1) ? r1 : r2);
            u64 wv = __shfl_sync(0xffffffffu, myw, owner);
            bool alive = vA[t] && !((wv >> (i & 63)) & 1ull);
            if (alive) { r0 |= bufA[t][0]; r1 |= bufA[t][1]; r2 |= bufA[t][2]; }
            if (lane == 0) keep[i] = alive ? 1 : 0;
        }
        // prefetch [base+16, base+24) into A
#pragma unroll
        for (int t = 0; t < 8; t++) {
            int ri = base + 16 + t;
            if (ri < NIN) {
                const u64* row = mask + (size_t)ri * NWRD;
                bufA[t][0] = row[w0]; bufA[t][1] = row[w1];
                bufA[t][2] = has2 ? row[w2] : 0;
                vA[t] = vs[ri];
            } else { bufA[t][0] = bufA[t][1] = bufA[t][2] = 0; vA[t] = 0; }
        }
        // process B
#pragma unroll
        for (int t = 0; t < 8; t++) {
            int i = base + 8 + t;
            if (i >= NIN) break;
            int iw = i >> 6;
            int sel = iw >> 5, owner = iw & 31;
            u64 myw = (sel == 0) ? r0 : ((sel == 1) ? r1 : r2);
            u64 wv = __shfl_sync(0xffffffffu, myw, owner);
            bool alive = vB[t] && !((wv >> (i & 63)) & 1ull);
            if (alive) { r0 |= bufB[t][0]; r1 |= bufB[t][1]; r2 |= bufB[t][2]; }
            if (lane == 0) keep[i] = alive ? 1 : 0;
        }
    }
}

// ---------------- misc outputs: zero rois region + roi_indices ----------------
__global__ void misc_kernel(float* __restrict__ out) {
    int gid = blockIdx.x * blockDim.x + threadIdx.x;
    if (gid < NB * NOUTP * 4) out[OFF_ROIS + gid] = 0.f;
    if (gid < NB * NOUTP) out[OFF_INDS + gid] = (float)(gid / NOUTP);
}

__global__ void anchors_kernel(float* __restrict__ out) {
    int r = blockIdx.x * blockDim.x + threadIdx.x;
    if (r >= NA) return;
    int p = r / 9, a = r % 9;
    int y = p >> 6, x = p & 63;
    float by1, bx1, by2, bx2;
    base_anchor(a, by1, bx1, by2, bx2);
    float fy = (float)(y * 16), fx = (float)(x * 16);
    float* o = out + OFF_ANCH + (size_t)r * 4;
    o[0] = fy + by1; o[1] = fx + bx1; o[2] = fy + by2; o[3] = fx + bx2;
}

// ---------------- compaction: rank = cumsum(keep)-1, scatter rank<300 ----------------
__global__ void __launch_bounds__(256) finalize_kernel(float* __restrict__ out) {
    int b = blockIdx.x;
    int tid = threadIdx.x;
    __shared__ int ssum[256];
    const unsigned char* keep = g_keep + b * NIN;
    unsigned char kl[24];
    int start = tid * 24;
    int cnt = 0;
#pragma unroll
    for (int t = 0; t < 24; t++) {
        int i = start + t;
        kl[t] = (i < NIN) ? keep[i] : 0;
        cnt += kl[t];
    }
    ssum[tid] = cnt;
    __syncthreads();
    for (int off = 1; off < 256; off <<= 1) {
        int v = (tid >= off) ? ssum[tid - off] : 0;
        __syncthreads();
        ssum[tid] += v;
        __syncthreads();
    }
    int r = ssum[tid] - cnt;  // exclusive prefix
    const float4* rs = (const float4*)g_rois_s;
#pragma unroll
    for (int t = 0; t < 24; t++) {
        if (kl[t]) {
            if (r < NOUTP) {
                int i = start + t;
                float4 bx = rs[(size_t)b * NPAD + i];
                float* o = out + OFF_ROIS + (size_t)(b * NOUTP + r) * 4;
                o[0] = bx.x; o[1] = bx.y; o[2] = bx.z; o[3] = bx.w;
            }
            r++;
        }
    }
}

// ---------------- launch ----------------
extern "C" void kernel_launch(void* const* d_in, const int* in_sizes, int n_in,
                              void* d_out, int out_size) {
    const float* x       = (const float*)d_in[0];
    const float* conv_w  = (const float*)d_in[1];
    const float* conv_b  = (const float*)d_in[2];
    const float* score_w = (const float*)d_in[3];
    const float* score_b = (const float*)d_in[4];
    const float* loc_w   = (const float*)d_in[5];
    const float* loc_b   = (const float*)d_in[6];
    float* out = (float*)d_out;

    conv3x3_kernel<<<dim3(16, 16, NB), 256>>>(x, conv_w, conv_b);
    heads_kernel<<<dim3(32, NB), 128>>>(score_w, score_b, loc_w, loc_b, out);
    pad_keys_kernel<<<(NB * (NSORT - NA) + 255) / 256, 256>>>();

    bitonic_local_sort<<<NB * NSORT / 4096, 1024>>>();
    for (int k = 8192; k <= NSORT; k <<= 1) {
        for (int j = k >> 1; j >= 4096; j >>= 1)
            bitonic_global_step<<<NB * NSORT / 256, 256>>>(k, j);
        bitonic_local_merge<<<NB * NSORT / 4096, 1024>>>(k);
    }

    gather_kernel<<<(NB * NIN + 255) / 256, 256>>>();
    mask_kernel<<<dim3(NWRD, NWRD, NB), 64>>>();
    nms_scan_kernel<<<NB, 32>>>();
    misc_kernel<<<(NB * NOUTP * 4 + 255) / 256, 256>>>(out);
    anchors_kernel<<<(NA + 255) / 256, 256>>>(out);
    finalize_kernel<<<NB, 256>>>(out);
}